// round 9
// baseline (speedup 1.0000x reference)
#include <cuda_runtime.h>
#include <math.h>

// Problem constants (fixed shapes)
#define B_   4
#define C_   64
#define H_   282
#define W_   282
#define P_   12000
#define HW_  (H_ * W_)        // 79524
#define NQ_  (HW_ / 4)        // 19881 float4-quads per channel image
#define QW_  4                // quads per gather warp (fine granularity)
#define WPB_ ((NQ_ + QW_ - 1) / QW_)    // 4971 warp-tiles per batch (last: 1 quad)
#define GW_  (B_ * WPB_)                // 19884 gather warps
#define GBLK_ (GW_ / 4)                 // 4971 blocks of 4 warps (exact)

#define PT_  (P_ / 32)        // 375 pillar tiles (exact)
#define CT_  (C_ / 32)        // 2  channel tiles
#define TRANS_BLOCKS_ (B_ * PT_ * CT_)            // 3000
#define IDX_BLOCKS_   ((B_ * P_ + 255) / 256)     // 188

// Scratch (device globals; zero-initialized at module load).
// g_winner: single plane, (p+1) of winning pillar, 0 = empty; self-reset by
// the owning gather warp (sole reader) -> no reset kernel, no replication.
__device__ __align__(16) int   g_winner[B_ * HW_];
__device__ __align__(16) float g_tf[B_ * P_ * C_];     // feats transposed to (B, P, C)

// ---------------------------------------------------------------------------
// Kernel 1 (fused): blocks [0, 3000) transpose feats (B,C,P) -> g_tf (B,P,C)
// via 32x32 smem tiles; blocks [3000, 3188) compute per-pillar cells and
// atomicMax(p+1) into g_winner (sequential last-update-wins == max p).
// Index math matches XLA fast-math lowering: (x + 22) * 6.25f (bit-verified).
// ---------------------------------------------------------------------------
__global__ void k_prep(const float* __restrict__ feats,
                       const float* __restrict__ pin) {
    if (blockIdx.x < TRANS_BLOCKS_) {
        __shared__ float tile[32][33];
        int bid   = blockIdx.x;
        int b     = bid / (PT_ * CT_);
        int rem   = bid - b * (PT_ * CT_);
        int ctile = rem / PT_;
        int ptile = rem - ctile * PT_;
        int tx = threadIdx.x & 31;
        int ty = threadIdx.x >> 5;

        const float* src = feats + ((size_t)b * C_ + ctile * 32) * P_ + ptile * 32;
        #pragma unroll
        for (int i = 0; i < 4; i++) {
            int cl = ty + 8 * i;
            tile[cl][tx] = src[(size_t)cl * P_ + tx];
        }
        __syncthreads();
        float* dst = g_tf + ((size_t)b * P_ + ptile * 32) * C_ + ctile * 32;
        #pragma unroll
        for (int i = 0; i < 4; i++) {
            int pl = ty + 8 * i;
            dst[(size_t)pl * C_ + tx] = tile[tx][pl];
        }
    } else {
        int i = (blockIdx.x - TRANS_BLOCKS_) * 256 + threadIdx.x;
        if (i >= B_ * P_) return;
        int b = i / P_;
        int p = i - b * P_;

        float x = pin[(b * 2 + 0) * P_ + p];
        if (x == 0.0f) return;            // invalid pillars dropped (OOB in ref)
        float y = pin[(b * 2 + 1) * P_ + p];

        int xg = (int)floorf(__fmul_rn(__fadd_rn(x, 22.0f), 6.25f));
        int yg = (int)floorf(__fmul_rn(__fadd_rn(y, 22.0f), 6.25f));
        xg = min(max(xg, 0), W_ - 1);
        yg = min(max(yg, 0), H_ - 1);
        atomicMax(&g_winner[b * HW_ + yg * W_ + xg], p + 1);
    }
}

// ---------------------------------------------------------------------------
// Kernel 2: GATHER at near-k_zero granularity. Warp = (b, 4-quad tile);
// lane = cg*4 + qi, qi in [0,4) the quad, cg in [0,8) the channel group of 8.
//  - lanes 0..3 read the tile's 4 winner int4s (one coalesced 64B read of
//    the single shared plane), __shfl_sync broadcasts to all cg groups, the
//    same lanes self-reset (warp-scoped ownership -> race-free, no barrier),
//  - thread: up to 8 float4 gathers (its 32B channel-slice of each of the 4
//    winning pillars' contiguous transposed-feature rows) + 8 coalesced
//    float4 stores (register 4x4 transpose).
// 19884 warps in 4971 shallow 128-thread blocks: hardware work-stealing
// balances the grid (k_zero-style), killing the multi-CTA spread/tail that
// pinned all coarse-block variants at ~24us.
// ---------------------------------------------------------------------------
__global__ void __launch_bounds__(128) k_gather(float4* __restrict__ out) {
    int wg = blockIdx.x * 4 + (threadIdx.x >> 5);   // global warp id, < GW_
    int b     = wg / WPB_;
    int tile  = wg - b * WPB_;
    int qbase = tile * QW_;
    int nq    = min(QW_, NQ_ - qbase);              // last tile per batch: 1

    int lane = threadIdx.x & 31;
    int qi   = lane & 3;
    int cg   = lane >> 2;                           // 0..7

    // ---- winner load (lanes 0..3), broadcast, self-reset ----
    int4* w4 = (int4*)g_winner;
    int gi = b * NQ_ + qbase + qi;
    bool loader = (cg == 0) & (qi < nq);
    int4 wl = make_int4(0, 0, 0, 0);
    if (loader) wl = w4[gi];

    int4 w;
    w.x = __shfl_sync(0xffffffffu, wl.x, qi);       // source lane qi has cg==0
    w.y = __shfl_sync(0xffffffffu, wl.y, qi);
    w.z = __shfl_sync(0xffffffffu, wl.z, qi);
    w.w = __shfl_sync(0xffffffffu, wl.w, qi);

    if (loader) w4[gi] = make_int4(0, 0, 0, 0);     // self-reset for next call
    if (qi >= nq) return;

    // ---- gather: this thread's 8 channels [cg*8, cg*8+8) of 4 pillars ----
    const float* tb = g_tf + (size_t)b * P_ * C_ + cg * 8;
    const float4* fx = (w.x > 0) ? (const float4*)(tb + (size_t)(w.x - 1) * C_) : nullptr;
    const float4* fy = (w.y > 0) ? (const float4*)(tb + (size_t)(w.y - 1) * C_) : nullptr;
    const float4* fz = (w.z > 0) ? (const float4*)(tb + (size_t)(w.z - 1) * C_) : nullptr;
    const float4* fw = (w.w > 0) ? (const float4*)(tb + (size_t)(w.w - 1) * C_) : nullptr;

    const float4 Z = make_float4(0.f, 0.f, 0.f, 0.f);
    float4 vx0 = fx ? __ldg(fx)     : Z,  vx1 = fx ? __ldg(fx + 1) : Z;
    float4 vy0 = fy ? __ldg(fy)     : Z,  vy1 = fy ? __ldg(fy + 1) : Z;
    float4 vz0 = fz ? __ldg(fz)     : Z,  vz1 = fz ? __ldg(fz + 1) : Z;
    float4 vw0 = fw ? __ldg(fw)     : Z,  vw1 = fw ? __ldg(fw + 1) : Z;

    // ---- 8 coalesced float4 stores (4x4 register transpose) ----
    float4* ob = out + ((size_t)b * C_ + cg * 8) * NQ_ + qbase + qi;
    ob[0 * (size_t)NQ_] = make_float4(vx0.x, vy0.x, vz0.x, vw0.x);
    ob[1 * (size_t)NQ_] = make_float4(vx0.y, vy0.y, vz0.y, vw0.y);
    ob[2 * (size_t)NQ_] = make_float4(vx0.z, vy0.z, vz0.z, vw0.z);
    ob[3 * (size_t)NQ_] = make_float4(vx0.w, vy0.w, vz0.w, vw0.w);
    ob[4 * (size_t)NQ_] = make_float4(vx1.x, vy1.x, vz1.x, vw1.x);
    ob[5 * (size_t)NQ_] = make_float4(vx1.y, vy1.y, vz1.y, vw1.y);
    ob[6 * (size_t)NQ_] = make_float4(vx1.z, vy1.z, vz1.z, vw1.z);
    ob[7 * (size_t)NQ_] = make_float4(vx1.w, vy1.w, vz1.w, vw1.w);
}

// ---------------------------------------------------------------------------
extern "C" void kernel_launch(void* const* d_in, const int* in_sizes, int n_in,
                              void* d_out, int out_size) {
    const float* pfn_input  = (const float*)d_in[0];   // (4, 2, 12000, 1)
    const float* pfn_output = (const float*)d_in[1];   // (4, 64, 12000)
    float* out = (float*)d_out;                        // (4, 64, 282, 282)

    k_prep  <<<TRANS_BLOCKS_ + IDX_BLOCKS_, 256>>>(pfn_output, pfn_input);
    k_gather<<<GBLK_,                       128>>>((float4*)out);
}